// round 1
// baseline (speedup 1.0000x reference)
#include <cuda_runtime.h>

#define BB 8
#define C_IN 64
#define C_OUT 128
#define HH 256
#define WW 256
#define NK 8

#define TH 16
#define TW 32
#define COT 8

__device__ float g_pooled[BB * C_IN];
__device__ float g_attn[BB * NK];
__device__ float g_mixed[BB * C_OUT * C_IN * 9];

// ---------------- Kernel 1: global average pool per (b, c_in) ----------------
__global__ void pool_kernel(const float* __restrict__ x) {
    int idx = blockIdx.x;  // b*C_IN + ci
    const float4* p = reinterpret_cast<const float4*>(x + (size_t)idx * (HH * WW));
    float s = 0.f;
    for (int i = threadIdx.x; i < (HH * WW) / 4; i += blockDim.x) {
        float4 v = p[i];
        s += v.x + v.y + v.z + v.w;
    }
    __shared__ float red[256];
    red[threadIdx.x] = s;
    __syncthreads();
    for (int off = 128; off > 0; off >>= 1) {
        if (threadIdx.x < off) red[threadIdx.x] += red[threadIdx.x + off];
        __syncthreads();
    }
    if (threadIdx.x == 0) g_pooled[idx] = red[0] * (1.0f / (HH * WW));
}

// ---------------- Kernel 2: logits + softmax -> attention weights ----------------
__global__ void attn_kernel(const float* __restrict__ attn_w,
                            const float* __restrict__ attn_b) {
    __shared__ float lg[BB * NK];
    int t = threadIdx.x;
    if (t < BB * NK) {
        int b = t / NK, n = t % NK;
        float s = attn_b[n];
        #pragma unroll 8
        for (int c = 0; c < C_IN; c++) s += g_pooled[b * C_IN + c] * attn_w[n * C_IN + c];
        lg[t] = s;
    }
    __syncthreads();
    if (t < BB) {
        float m = -1e30f;
        for (int n = 0; n < NK; n++) m = fmaxf(m, lg[t * NK + n]);
        float e[NK];
        float sum = 0.f;
        for (int n = 0; n < NK; n++) { e[n] = expf(lg[t * NK + n] - m); sum += e[n]; }
        float inv = 1.0f / sum;
        for (int n = 0; n < NK; n++) g_attn[t * NK + n] = e[n] * inv;
    }
}

// ---------------- Kernel 3: mix kernel bank by attention ----------------
__global__ void mix_kernel(const float* __restrict__ bank) {
    const int R = C_OUT * C_IN * 9;
    int i = blockIdx.x * blockDim.x + threadIdx.x;
    if (i >= BB * R) return;
    int b = i / R, r = i - b * R;
    float s = 0.f;
    #pragma unroll
    for (int n = 0; n < NK; n++) s += g_attn[b * NK + n] * bank[(size_t)n * R + r];
    g_mixed[i] = s;
}

// ---------------- Kernel 4: per-sample 3x3 conv with mixed weights ----------------
// Block: 256 threads = 8 warps. Warp w handles c_out = cobase + w.
// Lane = output column within a 32-wide tile; 16 output rows per thread (acc[16]).
// Per c_in iteration: cooperative halo tile load (34x18) into smem, then a
// row-sliding loop: each smem row read once (3 conflict-free LDS: cols lane,
// lane+1, lane+2) feeding kh = 0,1,2 of three accumulator rows.
__global__ void __launch_bounds__(256) conv_kernel(const float* __restrict__ x,
                                                   float* __restrict__ out) {
    __shared__ float sx[TH + 2][TW + 2];
    __shared__ float swt[COT][9];

    int tid = threadIdx.x;
    int lane = tid & 31;
    int wrp = tid >> 5;
    int gx0 = blockIdx.x * TW;
    int gy0 = blockIdx.y * TH;
    int bz = blockIdx.z;               // b * (C_OUT/COT) + cog
    int b = bz >> 4;                   // C_OUT/COT = 16
    int cobase = (bz & 15) * COT;
    int co = cobase + wrp;

    float acc[TH];
    #pragma unroll
    for (int i = 0; i < TH; i++) acc[i] = 0.f;

    const float* xb = x + (size_t)b * C_IN * (HH * WW);

    for (int ci = 0; ci < C_IN; ci++) {
        const float* xp = xb + (size_t)ci * (HH * WW);
        // cooperative halo tile load (zero padding at image borders)
        #pragma unroll
        for (int i = tid; i < (TH + 2) * (TW + 2); i += 256) {
            int r = i / (TW + 2);
            int c = i - r * (TW + 2);
            int y = gy0 + r - 1;
            int xc = gx0 + c - 1;
            float v = 0.f;
            if (y >= 0 && y < HH && xc >= 0 && xc < WW) v = xp[y * WW + xc];
            sx[r][c] = v;
        }
        if (tid < COT * 9) {
            int col = tid / 9, t = tid - col * 9;
            swt[col][t] =
                g_mixed[(((size_t)b * C_OUT + cobase + col) * C_IN + ci) * 9 + t];
        }
        __syncthreads();

        float w0 = swt[wrp][0], w1 = swt[wrp][1], w2 = swt[wrp][2];
        float w3 = swt[wrp][3], w4 = swt[wrp][4], w5 = swt[wrp][5];
        float w6 = swt[wrp][6], w7 = swt[wrp][7], w8 = swt[wrp][8];

        #pragma unroll
        for (int r = 0; r < TH + 2; r++) {
            float a = sx[r][lane];
            float m = sx[r][lane + 1];
            float c2 = sx[r][lane + 2];
            if (r < TH) {          // kh = 0 for output row r
                acc[r] = fmaf(a, w0, fmaf(m, w1, fmaf(c2, w2, acc[r])));
            }
            if (r >= 1 && r - 1 < TH) {  // kh = 1 for output row r-1
                acc[r - 1] = fmaf(a, w3, fmaf(m, w4, fmaf(c2, w5, acc[r - 1])));
            }
            if (r >= 2) {          // kh = 2 for output row r-2
                acc[r - 2] = fmaf(a, w6, fmaf(m, w7, fmaf(c2, w8, acc[r - 2])));
            }
        }
        __syncthreads();
    }

    float* op = out + (((size_t)b * C_OUT + co) * HH + gy0) * WW + gx0 + lane;
    #pragma unroll
    for (int o = 0; o < TH; o++) op[o * WW] = acc[o];
}

extern "C" void kernel_launch(void* const* d_in, const int* in_sizes, int n_in,
                              void* d_out, int out_size) {
    const float* x    = (const float*)d_in[0];
    const float* bank = (const float*)d_in[1];
    const float* aw   = (const float*)d_in[2];
    const float* ab   = (const float*)d_in[3];
    float* out = (float*)d_out;

    pool_kernel<<<BB * C_IN, 256>>>(x);
    attn_kernel<<<1, 64>>>(aw, ab);
    mix_kernel<<<(BB * C_OUT * C_IN * 9 + 255) / 256, 256>>>(bank);

    dim3 g(WW / TW, HH / TH, BB * (C_OUT / COT));
    conv_kernel<<<g, 256>>>(x, out);
}

// round 2
// speedup vs baseline: 1.2481x; 1.2481x over previous
#include <cuda_runtime.h>

#define BB 8
#define C_IN 64
#define C_OUT 128
#define HH 256
#define WW 256
#define NK 8

#define TH 16
#define TW 64
#define COT 16   // c_out per block (8 warps x 2 each)

__device__ float g_pooled[BB * C_IN];
__device__ float g_attn[BB * NK];
__device__ float g_mixed[BB * C_OUT * C_IN * 9];

typedef unsigned long long ull;

__device__ __forceinline__ ull pk(float lo, float hi) {
    ull r;
    asm("mov.b64 %0, {%1, %2};" : "=l"(r) : "f"(lo), "f"(hi));
    return r;
}
__device__ __forceinline__ void upk(float& lo, float& hi, ull v) {
    asm("mov.b64 {%0, %1}, %2;" : "=f"(lo), "=f"(hi) : "l"(v));
}
__device__ __forceinline__ ull ffma2(ull a, ull b, ull c) {
    ull d;
    asm("fma.rn.f32x2 %0, %1, %2, %3;" : "=l"(d) : "l"(a), "l"(b), "l"(c));
    return d;
}

// ---------------- Kernel 1: global average pool per (b, c_in) ----------------
__global__ void pool_kernel(const float* __restrict__ x) {
    int idx = blockIdx.x;  // b*C_IN + ci
    const float4* p = reinterpret_cast<const float4*>(x + (size_t)idx * (HH * WW));
    float s = 0.f;
    for (int i = threadIdx.x; i < (HH * WW) / 4; i += blockDim.x) {
        float4 v = p[i];
        s += v.x + v.y + v.z + v.w;
    }
    __shared__ float red[256];
    red[threadIdx.x] = s;
    __syncthreads();
    for (int off = 128; off > 0; off >>= 1) {
        if (threadIdx.x < off) red[threadIdx.x] += red[threadIdx.x + off];
        __syncthreads();
    }
    if (threadIdx.x == 0) g_pooled[idx] = red[0] * (1.0f / (HH * WW));
}

// ---------------- Kernel 2: logits + softmax -> attention weights ----------------
__global__ void attn_kernel(const float* __restrict__ attn_w,
                            const float* __restrict__ attn_b) {
    __shared__ float lg[BB * NK];
    int t = threadIdx.x;
    if (t < BB * NK) {
        int b = t / NK, n = t % NK;
        float s = attn_b[n];
        #pragma unroll 8
        for (int c = 0; c < C_IN; c++) s += g_pooled[b * C_IN + c] * attn_w[n * C_IN + c];
        lg[t] = s;
    }
    __syncthreads();
    if (t < BB) {
        float m = -1e30f;
        for (int n = 0; n < NK; n++) m = fmaxf(m, lg[t * NK + n]);
        float e[NK];
        float sum = 0.f;
        for (int n = 0; n < NK; n++) { e[n] = expf(lg[t * NK + n] - m); sum += e[n]; }
        float inv = 1.0f / sum;
        for (int n = 0; n < NK; n++) g_attn[t * NK + n] = e[n] * inv;
    }
}

// ---------------- Kernel 3: mix kernel bank by attention ----------------
__global__ void mix_kernel(const float* __restrict__ bank) {
    const int R = C_OUT * C_IN * 9;
    int i = blockIdx.x * blockDim.x + threadIdx.x;
    if (i >= BB * R) return;
    int b = i / R, r = i - b * R;
    float s = 0.f;
    #pragma unroll
    for (int n = 0; n < NK; n++) s += g_attn[b * NK + n] * bank[(size_t)n * R + r];
    g_mixed[i] = s;
}

// ---------------- Kernel 4: conv with packed f32x2 FMA ----------------
// Block: 256 threads = 8 warps. Tile: 64 wide x 16 tall, 16 c_out.
// Warp w handles c_out {cobase+w, cobase+8+w}. Lane covers output columns
// lane and lane+32, packed into one f32x2. Row-sliding loop: each smem row
// read once (6 conflict-free LDS), feeding 18 FFMA2 (2 c_out x 3 kh-rows x 3 kw).
__global__ void __launch_bounds__(256, 2) conv_kernel(const float* __restrict__ x,
                                                      float* __restrict__ out) {
    __shared__ float sx[TH + 2][TW + 2];
    __shared__ float swt[COT][9];

    int tid = threadIdx.x;
    int lane = tid & 31;
    int wrp = tid >> 5;
    int gx0 = blockIdx.x * TW;
    int gy0 = blockIdx.y * TH;
    int bz = blockIdx.z;               // b * (C_OUT/COT) + cog
    int b = bz >> 3;                   // C_OUT/COT = 8
    int cobase = (bz & 7) * COT;

    ull accA[TH], accB[TH];
    #pragma unroll
    for (int i = 0; i < TH; i++) { accA[i] = 0ULL; accB[i] = 0ULL; }

    const float* xb = x + (size_t)b * C_IN * (HH * WW);

    for (int ci = 0; ci < C_IN; ci++) {
        const float* xp = xb + (size_t)ci * (HH * WW);
        // cooperative halo tile load (zero padding at image borders)
        #pragma unroll
        for (int i = tid; i < (TH + 2) * (TW + 2); i += 256) {
            int r = i / (TW + 2);
            int c = i - r * (TW + 2);
            int y = gy0 + r - 1;
            int xc = gx0 + c - 1;
            float v = 0.f;
            if (y >= 0 && y < HH && xc >= 0 && xc < WW) v = xp[y * WW + xc];
            sx[r][c] = v;
        }
        if (tid < COT * 9) {
            int col = tid / 9, t = tid - col * 9;
            swt[col][t] =
                g_mixed[(((size_t)b * C_OUT + cobase + col) * C_IN + ci) * 9 + t];
        }
        __syncthreads();

        // packed weights (w, w) for both c_outs of this warp
        ull wA[9], wB[9];
        #pragma unroll
        for (int t = 0; t < 9; t++) {
            float a = swt[wrp][t];
            float c2 = swt[wrp + 8][t];
            wA[t] = pk(a, a);
            wB[t] = pk(c2, c2);
        }

        #pragma unroll
        for (int r = 0; r < TH + 2; r++) {
            float a0 = sx[r][lane],      a1 = sx[r][lane + 1],      a2 = sx[r][lane + 2];
            float b0 = sx[r][lane + 32], b1 = sx[r][lane + 33],     b2 = sx[r][lane + 34];
            ull p0 = pk(a0, b0);
            ull p1 = pk(a1, b1);
            ull p2 = pk(a2, b2);
            if (r < TH) {  // kh = 0 for output row r
                accA[r] = ffma2(p0, wA[0], ffma2(p1, wA[1], ffma2(p2, wA[2], accA[r])));
                accB[r] = ffma2(p0, wB[0], ffma2(p1, wB[1], ffma2(p2, wB[2], accB[r])));
            }
            if (r >= 1 && r - 1 < TH) {  // kh = 1 for output row r-1
                accA[r-1] = ffma2(p0, wA[3], ffma2(p1, wA[4], ffma2(p2, wA[5], accA[r-1])));
                accB[r-1] = ffma2(p0, wB[3], ffma2(p1, wB[4], ffma2(p2, wB[5], accB[r-1])));
            }
            if (r >= 2) {  // kh = 2 for output row r-2
                accA[r-2] = ffma2(p0, wA[6], ffma2(p1, wA[7], ffma2(p2, wA[8], accA[r-2])));
                accB[r-2] = ffma2(p0, wB[6], ffma2(p1, wB[7], ffma2(p2, wB[8], accB[r-2])));
            }
        }
        __syncthreads();
    }

    int co0 = cobase + wrp;
    int co1 = cobase + 8 + wrp;
    float* opA = out + (((size_t)b * C_OUT + co0) * HH + gy0) * WW + gx0;
    float* opB = out + (((size_t)b * C_OUT + co1) * HH + gy0) * WW + gx0;
    #pragma unroll
    for (int o = 0; o < TH; o++) {
        float lo, hi;
        upk(lo, hi, accA[o]);
        opA[o * WW + lane] = lo;
        opA[o * WW + lane + 32] = hi;
        upk(lo, hi, accB[o]);
        opB[o * WW + lane] = lo;
        opB[o * WW + lane + 32] = hi;
    }
}

extern "C" void kernel_launch(void* const* d_in, const int* in_sizes, int n_in,
                              void* d_out, int out_size) {
    const float* x    = (const float*)d_in[0];
    const float* bank = (const float*)d_in[1];
    const float* aw   = (const float*)d_in[2];
    const float* ab   = (const float*)d_in[3];
    float* out = (float*)d_out;

    pool_kernel<<<BB * C_IN, 256>>>(x);
    attn_kernel<<<1, 64>>>(aw, ab);
    mix_kernel<<<(BB * C_OUT * C_IN * 9 + 255) / 256, 256>>>(bank);

    dim3 g(WW / TW, HH / TH, BB * (C_OUT / COT));
    conv_kernel<<<g, 256>>>(x, out);
}